// round 4
// baseline (speedup 1.0000x reference)
#include <cuda_runtime.h>

#define N_NODES 100000
#define N_EDGES 1600000
#define D 128
#define SCAN_BLOCKS 98   // ceil(100000/1024)

// ---------------- scratch (static __device__, no allocation) ----------------
__device__ unsigned g_pb[(size_t)N_NODES * 64]; // X @ W_l as packed bf16x2 (agg operand)
__device__ float    g_q[(size_t)N_NODES * D];   // X @ W_r   (root path, fp32)
__device__ float    g_h[(size_t)N_NODES * D];   // layer-1 output
__device__ int      g_cnt[N_NODES];
__device__ int      g_offs[N_NODES + 1];
__device__ int      g_cursor[N_NODES];
__device__ int      g_bsums[SCAN_BLOCKS];
__device__ int      g_esrc[N_EDGES];
__device__ int      g_is64;

// ---------------- tf32 / bf16 helpers ----------------------------------------
__device__ __forceinline__ unsigned tf32(float f) {
    unsigned u;
    asm("cvt.rna.tf32.f32 %0, %1;" : "=r"(u) : "f"(f));
    return u;
}
__device__ __forceinline__ void mma_tf32(float c[4], const unsigned a[4], const unsigned b[2]) {
    asm volatile(
        "mma.sync.aligned.m16n8k8.row.col.f32.tf32.tf32.f32 "
        "{%0,%1,%2,%3}, {%4,%5,%6,%7}, {%8,%9}, {%0,%1,%2,%3};\n"
        : "+f"(c[0]), "+f"(c[1]), "+f"(c[2]), "+f"(c[3])
        : "r"(a[0]), "r"(a[1]), "r"(a[2]), "r"(a[3]), "r"(b[0]), "r"(b[1]));
}
__device__ __forceinline__ unsigned pack_bf16x2(float lo, float hi) {
    unsigned r;
    asm("cvt.rn.bf16x2.f32 %0, %1, %2;" : "=r"(r) : "f"(hi), "f"(lo));  // hi->[31:16], lo->[15:0]
    return r;
}
// exact bf16 -> f32 (bit placement)
__device__ __forceinline__ float bf_lo(unsigned u) { return __uint_as_float(u << 16); }
__device__ __forceinline__ float bf_hi(unsigned u) { return __uint_as_float(u & 0xffff0000u); }

// ---------------- edge-index dtype detection ---------------------------------
__global__ void k_detect(const int* __restrict__ e) {
    __shared__ int nz;
    if (threadIdx.x == 0) nz = 0;
    __syncthreads();
    if (e[2 * threadIdx.x + 1] != 0) atomicAdd(&nz, 1);
    __syncthreads();
    if (threadIdx.x == 0) g_is64 = (nz == 0) ? 1 : 0;
}

__device__ __forceinline__ int load_idx(const int* __restrict__ e, long long pos, int is64) {
    return is64 ? e[2 * pos] : e[pos];
}

// ---------------- CSR build --------------------------------------------------
__global__ void k_zero_cnt() {
    int i = blockIdx.x * blockDim.x + threadIdx.x;
    if (i < N_NODES) g_cnt[i] = 0;
}

__global__ void k_hist(const int* __restrict__ e) {
    int i = blockIdx.x * blockDim.x + threadIdx.x;
    if (i < N_EDGES) {
        int d = load_idx(e, (long long)N_EDGES + i, g_is64);
        atomicAdd(&g_cnt[d], 1);
    }
}

__global__ void k_scan_blocks(int n) {
    __shared__ int s[1024];
    int i = blockIdx.x * 1024 + threadIdx.x;
    int v = (i < n) ? g_cnt[i] : 0;
    s[threadIdx.x] = v;
    __syncthreads();
    #pragma unroll
    for (int d = 1; d < 1024; d <<= 1) {
        int t = (threadIdx.x >= d) ? s[threadIdx.x - d] : 0;
        __syncthreads();
        s[threadIdx.x] += t;
        __syncthreads();
    }
    if (i < n) g_offs[i] = s[threadIdx.x] - v;      // exclusive within block
    if (threadIdx.x == 1023) g_bsums[blockIdx.x] = s[1023];
}

__global__ void k_scan_sums(int nb) {
    if (threadIdx.x == 0) {
        int run = 0;
        for (int b = 0; b < nb; b++) { int t = g_bsums[b]; g_bsums[b] = run; run += t; }
    }
}

__global__ void k_add_offs(int n, int e) {
    int i = blockIdx.x * 1024 + threadIdx.x;
    if (i < n) {
        int o = g_offs[i] + g_bsums[blockIdx.x];
        g_offs[i] = o;
        g_cursor[i] = o;
    }
    if (i == 0) g_offs[n] = e;
}

__global__ void k_fill(const int* __restrict__ e) {
    int i = blockIdx.x * blockDim.x + threadIdx.x;
    if (i >= N_EDGES) return;
    int is64 = g_is64;
    int d = load_idx(e, (long long)N_EDGES + i, is64);
    int s = load_idx(e, (long long)i, is64);
    int pos = atomicAdd(&g_cursor[d], 1);
    g_esrc[pos] = s;
}

// ---------------- fused dual GEMM: Pb = bf16(X@Wl), Q = X@Wr (tf32 MMA) -----
// 128-row tile per block. 512 threads = 16 warps:
//   warps 0-7  -> P (mat 0, bf16 out), warps 8-15 -> Q (mat 1, fp32 out)
__global__ __launch_bounds__(512) void k_gemm2(const float* __restrict__ Xe, int xsel,
                                               const float* __restrict__ Wl,
                                               const float* __restrict__ Wr, int n) {
    __shared__ unsigned As[128][20];       // [row][k] stride 20 (16 data + pad)
    __shared__ unsigned Bs[2][16][136];    // [mat][k][col] stride 136
    const float* __restrict__ X = xsel ? g_h : Xe;

    int tid = threadIdx.x;
    int wid = tid >> 5, lane = tid & 31;
    int mat = wid >> 3;             // 0 = P, 1 = Q
    int wm = (wid & 7) >> 1;        // 0..3  (row tile)
    int wn = wid & 1;               // 0..1  (col tile)
    int gid = lane >> 2, tig = lane & 3;
    int row0 = blockIdx.x * 128;

    float c[2][8][4];
    #pragma unroll
    for (int mi = 0; mi < 2; mi++)
        #pragma unroll
        for (int ni = 0; ni < 8; ni++)
            #pragma unroll
            for (int j = 0; j < 4; j++) c[mi][ni][j] = 0.f;

    int arow = tid >> 2;            // 0..127
    int acol = (tid & 3) * 4;       // 0,4,8,12
    int brow = tid >> 5;            // 0..15
    int bcol = (tid & 31) * 4;      // 0..124

    const float* xr = X + (size_t)(row0 + arow) * 128 + acol;
    bool aval = (row0 + arow) < n;

    for (int kk = 0; kk < 128; kk += 16) {
        __syncthreads();
        {
            float4 v = make_float4(0.f, 0.f, 0.f, 0.f);
            if (aval) v = *(const float4*)(xr + kk);
            As[arow][acol + 0] = tf32(v.x);
            As[arow][acol + 1] = tf32(v.y);
            As[arow][acol + 2] = tf32(v.z);
            As[arow][acol + 3] = tf32(v.w);
        }
        {
            float4 vl = *(const float4*)(Wl + (size_t)(kk + brow) * 128 + bcol);
            float4 vr = *(const float4*)(Wr + (size_t)(kk + brow) * 128 + bcol);
            Bs[0][brow][bcol + 0] = tf32(vl.x);
            Bs[0][brow][bcol + 1] = tf32(vl.y);
            Bs[0][brow][bcol + 2] = tf32(vl.z);
            Bs[0][brow][bcol + 3] = tf32(vl.w);
            Bs[1][brow][bcol + 0] = tf32(vr.x);
            Bs[1][brow][bcol + 1] = tf32(vr.y);
            Bs[1][brow][bcol + 2] = tf32(vr.z);
            Bs[1][brow][bcol + 3] = tf32(vr.w);
        }
        __syncthreads();

        #pragma unroll
        for (int ks = 0; ks < 2; ks++) {
            unsigned a[2][4], b[8][2];
            #pragma unroll
            for (int mi = 0; mi < 2; mi++) {
                int r = wm * 32 + mi * 16 + gid;
                a[mi][0] = As[r][ks * 8 + tig];
                a[mi][1] = As[r + 8][ks * 8 + tig];
                a[mi][2] = As[r][ks * 8 + tig + 4];
                a[mi][3] = As[r + 8][ks * 8 + tig + 4];
            }
            #pragma unroll
            for (int ni = 0; ni < 8; ni++) {
                int col = wn * 64 + ni * 8 + gid;
                b[ni][0] = Bs[mat][ks * 8 + tig][col];
                b[ni][1] = Bs[mat][ks * 8 + tig + 4][col];
            }
            #pragma unroll
            for (int mi = 0; mi < 2; mi++)
                #pragma unroll
                for (int ni = 0; ni < 8; ni++)
                    mma_tf32(c[mi][ni], a[mi], b[ni]);
        }
    }

    // epilogue
    if (mat == 0) {
        // P path: pack to bf16x2 (cols cl, cl+1 -> one u32)
        #pragma unroll
        for (int mi = 0; mi < 2; mi++) {
            int r = row0 + wm * 32 + mi * 16 + gid;
            #pragma unroll
            for (int ni = 0; ni < 8; ni++) {
                int cl = wn * 64 + ni * 8 + tig * 2;
                if (r < n)
                    g_pb[(size_t)r * 64 + (cl >> 1)] = pack_bf16x2(c[mi][ni][0], c[mi][ni][1]);
                if (r + 8 < n)
                    g_pb[(size_t)(r + 8) * 64 + (cl >> 1)] = pack_bf16x2(c[mi][ni][2], c[mi][ni][3]);
            }
        }
    } else {
        #pragma unroll
        for (int mi = 0; mi < 2; mi++) {
            int r = row0 + wm * 32 + mi * 16 + gid;
            #pragma unroll
            for (int ni = 0; ni < 8; ni++) {
                int cl = wn * 64 + ni * 8 + tig * 2;
                if (r < n)
                    *(float2*)(g_q + (size_t)r * 128 + cl) = make_float2(c[mi][ni][0], c[mi][ni][1]);
                if (r + 8 < n)
                    *(float2*)(g_q + (size_t)(r + 8) * 128 + cl) = make_float2(c[mi][ni][2], c[mi][ni][3]);
            }
        }
    }
}

// ---------------- aggregation: out = [relu]( mean_agg(Pb) + b + Q ) ---------
// one warp per destination node; lane l owns cols 4l..4l+3 (uint2 = 4 bf16)
__global__ void k_agg(const float* __restrict__ bias, float* __restrict__ oext,
                      int osel, int do_relu) {
    int w = (blockIdx.x * blockDim.x + threadIdx.x) >> 5;
    if (w >= N_NODES) return;
    const unsigned* __restrict__ P = g_pb;
    const float* __restrict__ Q = g_q;
    float* __restrict__ out = osel ? oext : g_h;

    int lane = threadIdx.x & 31;
    int s0 = g_offs[w], s1 = g_offs[w + 1];

    float4 acc = make_float4(0.f, 0.f, 0.f, 0.f);
    int e = s0;
    for (; e + 4 <= s1; e += 4) {
        int i0 = g_esrc[e], i1 = g_esrc[e + 1], i2 = g_esrc[e + 2], i3 = g_esrc[e + 3];
        uint2 u0 = ((const uint2*)(P + (size_t)i0 * 64))[lane];
        uint2 u1 = ((const uint2*)(P + (size_t)i1 * 64))[lane];
        uint2 u2 = ((const uint2*)(P + (size_t)i2 * 64))[lane];
        uint2 u3 = ((const uint2*)(P + (size_t)i3 * 64))[lane];
        acc.x += (bf_lo(u0.x) + bf_lo(u1.x)) + (bf_lo(u2.x) + bf_lo(u3.x));
        acc.y += (bf_hi(u0.x) + bf_hi(u1.x)) + (bf_hi(u2.x) + bf_hi(u3.x));
        acc.z += (bf_lo(u0.y) + bf_lo(u1.y)) + (bf_lo(u2.y) + bf_lo(u3.y));
        acc.w += (bf_hi(u0.y) + bf_hi(u1.y)) + (bf_hi(u2.y) + bf_hi(u3.y));
    }
    for (; e < s1; e++) {
        int i0 = g_esrc[e];
        uint2 u0 = ((const uint2*)(P + (size_t)i0 * 64))[lane];
        acc.x += bf_lo(u0.x); acc.y += bf_hi(u0.x);
        acc.z += bf_lo(u0.y); acc.w += bf_hi(u0.y);
    }

    int deg = s1 - s0;
    float scale = 1.0f / (float)(deg > 0 ? deg : 1);
    float4 qv = ((const float4*)(Q + (size_t)w * 128))[lane];
    float4 bv = ((const float4*)bias)[lane];
    float4 r;
    r.x = fmaf(acc.x, scale, bv.x + qv.x);
    r.y = fmaf(acc.y, scale, bv.y + qv.y);
    r.z = fmaf(acc.z, scale, bv.z + qv.z);
    r.w = fmaf(acc.w, scale, bv.w + qv.w);
    if (do_relu) {
        r.x = fmaxf(r.x, 0.f); r.y = fmaxf(r.y, 0.f);
        r.z = fmaxf(r.z, 0.f); r.w = fmaxf(r.w, 0.f);
    }
    ((float4*)(out + (size_t)w * 128))[lane] = r;
}

// ---------------- launch -----------------------------------------------------
extern "C" void kernel_launch(void* const* d_in, const int* in_sizes, int n_in,
                              void* d_out, int out_size) {
    const float* x   = (const float*)d_in[0];
    const int*   ei  = (const int*)d_in[1];
    const float* W1l = (const float*)d_in[2];
    const float* b1  = (const float*)d_in[3];
    const float* W1r = (const float*)d_in[4];
    const float* W2l = (const float*)d_in[5];
    const float* b2  = (const float*)d_in[6];
    const float* W2r = (const float*)d_in[7];
    float* out = (float*)d_out;

    const int GEMM_GRID = (N_NODES + 127) / 128;      // 782
    const int EDGE_GRID = (N_EDGES + 255) / 256;
    const int AGG_GRID  = (N_NODES * 32 + 255) / 256;

    // ---- CSR build (dst-grouped pull lists) ----
    k_detect<<<1, 256>>>(ei);
    k_zero_cnt<<<(N_NODES + 255) / 256, 256>>>();
    k_hist<<<EDGE_GRID, 256>>>(ei);
    k_scan_blocks<<<SCAN_BLOCKS, 1024>>>(N_NODES);
    k_scan_sums<<<1, 32>>>(SCAN_BLOCKS);
    k_add_offs<<<SCAN_BLOCKS, 1024>>>(N_NODES, N_EDGES);
    k_fill<<<EDGE_GRID, 256>>>(ei);

    // ---- layer 1: transform-then-aggregate (aggregation is linear) ----
    k_gemm2<<<GEMM_GRID, 512>>>(x, 0, W1l, W1r, N_NODES);
    k_agg<<<AGG_GRID, 256>>>(b1, out, 0, 1);

    // ---- layer 2 ----
    k_gemm2<<<GEMM_GRID, 512>>>((const float*)0, 1, W2l, W2r, N_NODES);
    k_agg<<<AGG_GRID, 256>>>(b2, out, 1, 0);
}

// round 5
// speedup vs baseline: 1.4143x; 1.4143x over previous
#include <cuda_runtime.h>

#define N_NODES 100000
#define N_EDGES 1600000
#define D 128
#define SCAN_BLOCKS 98   // ceil(100000/1024)

// ---------------- scratch (static __device__, no allocation) ----------------
__device__ unsigned g_pb[(size_t)N_NODES * 64]; // X @ W_l as packed bf16x2 (agg operand)
__device__ float    g_q[(size_t)N_NODES * D];   // X @ W_r   (root path, fp32)
__device__ float    g_h[(size_t)N_NODES * D];   // layer-1 output
__device__ int      g_cnt[N_NODES];
__device__ int      g_offs[N_NODES + 1];
__device__ int      g_cursor[N_NODES];
__device__ int      g_bsums[SCAN_BLOCKS];
__device__ int      g_esrc[N_EDGES];
__device__ int      g_is64;

// ---------------- tf32 / bf16 helpers ----------------------------------------
__device__ __forceinline__ unsigned tf32(float f) {
    unsigned u;
    asm("cvt.rna.tf32.f32 %0, %1;" : "=r"(u) : "f"(f));
    return u;
}
__device__ __forceinline__ void mma_tf32(float c[4], const unsigned a[4], const unsigned b[2]) {
    asm volatile(
        "mma.sync.aligned.m16n8k8.row.col.f32.tf32.tf32.f32 "
        "{%0,%1,%2,%3}, {%4,%5,%6,%7}, {%8,%9}, {%0,%1,%2,%3};\n"
        : "+f"(c[0]), "+f"(c[1]), "+f"(c[2]), "+f"(c[3])
        : "r"(a[0]), "r"(a[1]), "r"(a[2]), "r"(a[3]), "r"(b[0]), "r"(b[1]));
}
__device__ __forceinline__ unsigned pack_bf16x2(float lo, float hi) {
    unsigned r;
    asm("cvt.rn.bf16x2.f32 %0, %1, %2;" : "=r"(r) : "f"(hi), "f"(lo));  // hi->[31:16], lo->[15:0]
    return r;
}
// exact bf16 -> f32 (bit placement)
__device__ __forceinline__ float bf_lo(unsigned u) { return __uint_as_float(u << 16); }
__device__ __forceinline__ float bf_hi(unsigned u) { return __uint_as_float(u & 0xffff0000u); }

// ---------------- edge-index dtype detection ---------------------------------
__global__ void k_detect(const int* __restrict__ e) {
    __shared__ int nz;
    if (threadIdx.x == 0) nz = 0;
    __syncthreads();
    if (e[2 * threadIdx.x + 1] != 0) atomicAdd(&nz, 1);
    __syncthreads();
    if (threadIdx.x == 0) g_is64 = (nz == 0) ? 1 : 0;
}

__device__ __forceinline__ int load_idx(const int* __restrict__ e, long long pos, int is64) {
    return is64 ? e[2 * pos] : e[pos];
}

// ---------------- CSR build --------------------------------------------------
__global__ void k_zero_cnt() {
    int i = blockIdx.x * blockDim.x + threadIdx.x;
    if (i < N_NODES) g_cnt[i] = 0;
}

__global__ void k_hist(const int* __restrict__ e) {
    int i = blockIdx.x * blockDim.x + threadIdx.x;
    if (i < N_EDGES) {
        int d = load_idx(e, (long long)N_EDGES + i, g_is64);
        atomicAdd(&g_cnt[d], 1);
    }
}

__global__ void k_scan_blocks(int n) {
    __shared__ int s[1024];
    int i = blockIdx.x * 1024 + threadIdx.x;
    int v = (i < n) ? g_cnt[i] : 0;
    s[threadIdx.x] = v;
    __syncthreads();
    #pragma unroll
    for (int d = 1; d < 1024; d <<= 1) {
        int t = (threadIdx.x >= d) ? s[threadIdx.x - d] : 0;
        __syncthreads();
        s[threadIdx.x] += t;
        __syncthreads();
    }
    if (i < n) g_offs[i] = s[threadIdx.x] - v;      // exclusive within block
    if (threadIdx.x == 1023) g_bsums[blockIdx.x] = s[1023];
}

__global__ void k_scan_sums(int nb) {
    if (threadIdx.x == 0) {
        int run = 0;
        for (int b = 0; b < nb; b++) { int t = g_bsums[b]; g_bsums[b] = run; run += t; }
    }
}

__global__ void k_add_offs(int n, int e) {
    int i = blockIdx.x * 1024 + threadIdx.x;
    if (i < n) {
        int o = g_offs[i] + g_bsums[blockIdx.x];
        g_offs[i] = o;
        g_cursor[i] = o;
    }
    if (i == 0) g_offs[n] = e;
}

__global__ void k_fill(const int* __restrict__ e) {
    int i = blockIdx.x * blockDim.x + threadIdx.x;
    if (i >= N_EDGES) return;
    int is64 = g_is64;
    int d = load_idx(e, (long long)N_EDGES + i, is64);
    int s = load_idx(e, (long long)i, is64);
    int pos = atomicAdd(&g_cursor[d], 1);
    g_esrc[pos] = s;
}

// ---------------- fused dual GEMM: Pb = bf16(X@Wl), Q = X@Wr (tf32 MMA) -----
// 128-row tile per block. 512 threads = 16 warps:
//   warps 0-7  -> P (mat 0, bf16 out), warps 8-15 -> Q (mat 1, fp32 out)
__global__ __launch_bounds__(512) void k_gemm2(const float* __restrict__ Xe, int xsel,
                                               const float* __restrict__ Wl,
                                               const float* __restrict__ Wr, int n) {
    __shared__ unsigned As[128][20];       // [row][k] stride 20 (16 data + pad)
    __shared__ unsigned Bs[2][16][136];    // [mat][k][col] stride 136
    const float* __restrict__ X = xsel ? g_h : Xe;

    int tid = threadIdx.x;
    int wid = tid >> 5, lane = tid & 31;
    int mat = wid >> 3;             // 0 = P, 1 = Q
    int wm = (wid & 7) >> 1;        // 0..3  (row tile)
    int wn = wid & 1;               // 0..1  (col tile)
    int gid = lane >> 2, tig = lane & 3;
    int row0 = blockIdx.x * 128;

    float c[2][8][4];
    #pragma unroll
    for (int mi = 0; mi < 2; mi++)
        #pragma unroll
        for (int ni = 0; ni < 8; ni++)
            #pragma unroll
            for (int j = 0; j < 4; j++) c[mi][ni][j] = 0.f;

    int arow = tid >> 2;            // 0..127
    int acol = (tid & 3) * 4;       // 0,4,8,12
    int brow = tid >> 5;            // 0..15
    int bcol = (tid & 31) * 4;      // 0..124

    const float* xr = X + (size_t)(row0 + arow) * 128 + acol;
    bool aval = (row0 + arow) < n;

    for (int kk = 0; kk < 128; kk += 16) {
        __syncthreads();
        {
            float4 v = make_float4(0.f, 0.f, 0.f, 0.f);
            if (aval) v = *(const float4*)(xr + kk);
            As[arow][acol + 0] = tf32(v.x);
            As[arow][acol + 1] = tf32(v.y);
            As[arow][acol + 2] = tf32(v.z);
            As[arow][acol + 3] = tf32(v.w);
        }
        {
            float4 vl = *(const float4*)(Wl + (size_t)(kk + brow) * 128 + bcol);
            float4 vr = *(const float4*)(Wr + (size_t)(kk + brow) * 128 + bcol);
            Bs[0][brow][bcol + 0] = tf32(vl.x);
            Bs[0][brow][bcol + 1] = tf32(vl.y);
            Bs[0][brow][bcol + 2] = tf32(vl.z);
            Bs[0][brow][bcol + 3] = tf32(vl.w);
            Bs[1][brow][bcol + 0] = tf32(vr.x);
            Bs[1][brow][bcol + 1] = tf32(vr.y);
            Bs[1][brow][bcol + 2] = tf32(vr.z);
            Bs[1][brow][bcol + 3] = tf32(vr.w);
        }
        __syncthreads();

        #pragma unroll
        for (int ks = 0; ks < 2; ks++) {
            unsigned a[2][4], b[8][2];
            #pragma unroll
            for (int mi = 0; mi < 2; mi++) {
                int r = wm * 32 + mi * 16 + gid;
                a[mi][0] = As[r][ks * 8 + tig];
                a[mi][1] = As[r + 8][ks * 8 + tig];
                a[mi][2] = As[r][ks * 8 + tig + 4];
                a[mi][3] = As[r + 8][ks * 8 + tig + 4];
            }
            #pragma unroll
            for (int ni = 0; ni < 8; ni++) {
                int col = wn * 64 + ni * 8 + gid;
                b[ni][0] = Bs[mat][ks * 8 + tig][col];
                b[ni][1] = Bs[mat][ks * 8 + tig + 4][col];
            }
            #pragma unroll
            for (int mi = 0; mi < 2; mi++)
                #pragma unroll
                for (int ni = 0; ni < 8; ni++)
                    mma_tf32(c[mi][ni], a[mi], b[ni]);
        }
    }

    // epilogue
    if (mat == 0) {
        #pragma unroll
        for (int mi = 0; mi < 2; mi++) {
            int r = row0 + wm * 32 + mi * 16 + gid;
            #pragma unroll
            for (int ni = 0; ni < 8; ni++) {
                int cl = wn * 64 + ni * 8 + tig * 2;
                if (r < n)
                    g_pb[(size_t)r * 64 + (cl >> 1)] = pack_bf16x2(c[mi][ni][0], c[mi][ni][1]);
                if (r + 8 < n)
                    g_pb[(size_t)(r + 8) * 64 + (cl >> 1)] = pack_bf16x2(c[mi][ni][2], c[mi][ni][3]);
            }
        }
    } else {
        #pragma unroll
        for (int mi = 0; mi < 2; mi++) {
            int r = row0 + wm * 32 + mi * 16 + gid;
            #pragma unroll
            for (int ni = 0; ni < 8; ni++) {
                int cl = wn * 64 + ni * 8 + tig * 2;
                if (r < n)
                    *(float2*)(g_q + (size_t)r * 128 + cl) = make_float2(c[mi][ni][0], c[mi][ni][1]);
                if (r + 8 < n)
                    *(float2*)(g_q + (size_t)(r + 8) * 128 + cl) = make_float2(c[mi][ni][2], c[mi][ni][3]);
            }
        }
    }
}

// ---------------- aggregation: out = [relu]( mean_agg(Pb) + b + Q ) ---------
// one warp per destination node; lane l owns cols 4l..4l+3 (uint2 = 4 bf16)
// 8-deep gather unroll to raise per-warp MLP (latency-bound loop).
__global__ void k_agg(const float* __restrict__ bias, float* __restrict__ oext,
                      int osel, int do_relu) {
    int w = (blockIdx.x * blockDim.x + threadIdx.x) >> 5;
    if (w >= N_NODES) return;
    const unsigned* __restrict__ P = g_pb;
    const float* __restrict__ Q = g_q;
    float* __restrict__ out = osel ? oext : g_h;

    int lane = threadIdx.x & 31;
    int s0 = g_offs[w], s1 = g_offs[w + 1];

    float4 acc0 = make_float4(0.f, 0.f, 0.f, 0.f);
    float4 acc1 = make_float4(0.f, 0.f, 0.f, 0.f);
    int e = s0;
    for (; e + 8 <= s1; e += 8) {
        int idx[8];
        #pragma unroll
        for (int j = 0; j < 8; j++) idx[j] = g_esrc[e + j];
        uint2 u[8];
        #pragma unroll
        for (int j = 0; j < 8; j++)
            u[j] = ((const uint2*)(P + (size_t)idx[j] * 64))[lane];
        #pragma unroll
        for (int j = 0; j < 8; j += 2) {
            acc0.x += bf_lo(u[j].x) + bf_lo(u[j + 1].x);
            acc0.y += bf_hi(u[j].x) + bf_hi(u[j + 1].x);
            acc0.z += bf_lo(u[j].y) + bf_lo(u[j + 1].y);
            acc0.w += bf_hi(u[j].y) + bf_hi(u[j + 1].y);
        }
    }
    for (; e + 2 <= s1; e += 2) {
        int i0 = g_esrc[e], i1 = g_esrc[e + 1];
        uint2 u0 = ((const uint2*)(P + (size_t)i0 * 64))[lane];
        uint2 u1 = ((const uint2*)(P + (size_t)i1 * 64))[lane];
        acc1.x += bf_lo(u0.x) + bf_lo(u1.x);
        acc1.y += bf_hi(u0.x) + bf_hi(u1.x);
        acc1.z += bf_lo(u0.y) + bf_lo(u1.y);
        acc1.w += bf_hi(u0.y) + bf_hi(u1.y);
    }
    if (e < s1) {
        int i0 = g_esrc[e];
        uint2 u0 = ((const uint2*)(P + (size_t)i0 * 64))[lane];
        acc1.x += bf_lo(u0.x); acc1.y += bf_hi(u0.x);
        acc1.z += bf_lo(u0.y); acc1.w += bf_hi(u0.y);
    }
    acc0.x += acc1.x; acc0.y += acc1.y; acc0.z += acc1.z; acc0.w += acc1.w;

    int deg = s1 - s0;
    float scale = 1.0f / (float)(deg > 0 ? deg : 1);
    float4 qv = ((const float4*)(Q + (size_t)w * 128))[lane];
    float4 bv = ((const float4*)bias)[lane];
    float4 r;
    r.x = fmaf(acc0.x, scale, bv.x + qv.x);
    r.y = fmaf(acc0.y, scale, bv.y + qv.y);
    r.z = fmaf(acc0.z, scale, bv.z + qv.z);
    r.w = fmaf(acc0.w, scale, bv.w + qv.w);
    if (do_relu) {
        r.x = fmaxf(r.x, 0.f); r.y = fmaxf(r.y, 0.f);
        r.z = fmaxf(r.z, 0.f); r.w = fmaxf(r.w, 0.f);
    }
    ((float4*)(out + (size_t)w * 128))[lane] = r;
}

// ---------------- launch -----------------------------------------------------
extern "C" void kernel_launch(void* const* d_in, const int* in_sizes, int n_in,
                              void* d_out, int out_size) {
    const float* x   = (const float*)d_in[0];
    const int*   ei  = (const int*)d_in[1];
    const float* W1l = (const float*)d_in[2];
    const float* b1  = (const float*)d_in[3];
    const float* W1r = (const float*)d_in[4];
    const float* W2l = (const float*)d_in[5];
    const float* b2  = (const float*)d_in[6];
    const float* W2r = (const float*)d_in[7];
    float* out = (float*)d_out;

    const int GEMM_GRID = (N_NODES + 127) / 128;      // 782
    const int EDGE_GRID = (N_EDGES + 255) / 256;
    const int AGG_GRID  = (N_NODES * 32 + 255) / 256;

    // ---- CSR build (dst-grouped pull lists) ----
    k_detect<<<1, 256>>>(ei);
    k_zero_cnt<<<(N_NODES + 255) / 256, 256>>>();
    k_hist<<<EDGE_GRID, 256>>>(ei);
    k_scan_blocks<<<SCAN_BLOCKS, 1024>>>(N_NODES);
    k_scan_sums<<<1, 32>>>(SCAN_BLOCKS);
    k_add_offs<<<SCAN_BLOCKS, 1024>>>(N_NODES, N_EDGES);
    k_fill<<<EDGE_GRID, 256>>>(ei);

    // ---- layer 1: transform-then-aggregate (aggregation is linear) ----
    k_gemm2<<<GEMM_GRID, 512>>>(x, 0, W1l, W1r, N_NODES);
    k_agg<<<AGG_GRID, 256>>>(b1, out, 0, 1);

    // ---- layer 2 ----
    k_gemm2<<<GEMM_GRID, 512>>>((const float*)0, 1, W2l, W2r, N_NODES);
    k_agg<<<AGG_GRID, 256>>>(b2, out, 1, 0);
}

// round 6
// speedup vs baseline: 1.4833x; 1.0488x over previous
#include <cuda_runtime.h>

#define N_NODES 100000
#define N_EDGES 1600000
#define D 128
#define SCAN_BLOCKS 98   // ceil(100000/1024)

// ---------------- scratch (static __device__, no allocation) ----------------
__device__ unsigned g_pb[(size_t)N_NODES * 64]; // X @ W_l as packed bf16x2 (agg operand)
__device__ float    g_q[(size_t)N_NODES * D];   // X @ W_r   (root path, fp32)
__device__ float    g_h[(size_t)N_NODES * D];   // layer-1 output
__device__ int      g_cnt[N_NODES];
__device__ int      g_offs[N_NODES + 1];
__device__ int      g_cursor[N_NODES];
__device__ int      g_bsums[SCAN_BLOCKS];
__device__ int      g_esrc[N_EDGES];
__device__ int      g_is64;

// ---------------- tf32 / bf16 helpers ----------------------------------------
__device__ __forceinline__ unsigned tf32(float f) {
    unsigned u;
    asm("cvt.rna.tf32.f32 %0, %1;" : "=r"(u) : "f"(f));
    return u;
}
__device__ __forceinline__ void mma_tf32(float c[4], const unsigned a[4], const unsigned b[2]) {
    asm volatile(
        "mma.sync.aligned.m16n8k8.row.col.f32.tf32.tf32.f32 "
        "{%0,%1,%2,%3}, {%4,%5,%6,%7}, {%8,%9}, {%0,%1,%2,%3};\n"
        : "+f"(c[0]), "+f"(c[1]), "+f"(c[2]), "+f"(c[3])
        : "r"(a[0]), "r"(a[1]), "r"(a[2]), "r"(a[3]), "r"(b[0]), "r"(b[1]));
}
__device__ __forceinline__ unsigned pack_bf16x2(float lo, float hi) {
    unsigned r;
    asm("cvt.rn.bf16x2.f32 %0, %1, %2;" : "=r"(r) : "f"(hi), "f"(lo));  // hi->[31:16], lo->[15:0]
    return r;
}
// exact bf16 -> f32 (bit placement)
__device__ __forceinline__ float bf_lo(unsigned u) { return __uint_as_float(u << 16); }
__device__ __forceinline__ float bf_hi(unsigned u) { return __uint_as_float(u & 0xffff0000u); }

// ---------------- edge-index dtype detect + counter zero (merged) ------------
__global__ void k_detect(const int* __restrict__ e) {
    int i = blockIdx.x * blockDim.x + threadIdx.x;
    if (i < N_NODES) g_cnt[i] = 0;
    if (blockIdx.x == 0) {
        __shared__ int nz;
        if (threadIdx.x == 0) nz = 0;
        __syncthreads();
        if (e[2 * threadIdx.x + 1] != 0) atomicAdd(&nz, 1);
        __syncthreads();
        if (threadIdx.x == 0) g_is64 = (nz == 0) ? 1 : 0;
    }
}

__device__ __forceinline__ int load_idx(const int* __restrict__ e, long long pos, int is64) {
    return is64 ? e[2 * pos] : e[pos];
}

// ---------------- CSR build --------------------------------------------------
__global__ void k_hist(const int* __restrict__ e) {
    int i = blockIdx.x * blockDim.x + threadIdx.x;
    if (i < N_EDGES) {
        int d = load_idx(e, (long long)N_EDGES + i, g_is64);
        atomicAdd(&g_cnt[d], 1);
    }
}

__global__ void k_scan_blocks(int n) {
    __shared__ int s[1024];
    int i = blockIdx.x * 1024 + threadIdx.x;
    int v = (i < n) ? g_cnt[i] : 0;
    s[threadIdx.x] = v;
    __syncthreads();
    #pragma unroll
    for (int d = 1; d < 1024; d <<= 1) {
        int t = (threadIdx.x >= d) ? s[threadIdx.x - d] : 0;
        __syncthreads();
        s[threadIdx.x] += t;
        __syncthreads();
    }
    if (i < n) g_offs[i] = s[threadIdx.x] - v;      // exclusive within block
    if (threadIdx.x == 1023) g_bsums[blockIdx.x] = s[1023];
}

__global__ void k_scan_sums(int nb) {
    if (threadIdx.x == 0) {
        int run = 0;
        for (int b = 0; b < nb; b++) { int t = g_bsums[b]; g_bsums[b] = run; run += t; }
    }
}

__global__ void k_add_offs(int n, int e) {
    int i = blockIdx.x * 1024 + threadIdx.x;
    if (i < n) {
        int o = g_offs[i] + g_bsums[blockIdx.x];
        g_offs[i] = o;
        g_cursor[i] = o;
    }
    if (i == 0) g_offs[n] = e;
}

__global__ void k_fill(const int* __restrict__ e) {
    int i = blockIdx.x * blockDim.x + threadIdx.x;
    if (i >= N_EDGES) return;
    int is64 = g_is64;
    int d = load_idx(e, (long long)N_EDGES + i, is64);
    int s = load_idx(e, (long long)i, is64);
    int pos = atomicAdd(&g_cursor[d], 1);
    g_esrc[pos] = s;
}

// ---------------- fused dual GEMM: Pb = bf16(X@Wl), Q = X@Wr (tf32 MMA) -----
__global__ __launch_bounds__(512) void k_gemm2(const float* __restrict__ Xe, int xsel,
                                               const float* __restrict__ Wl,
                                               const float* __restrict__ Wr, int n) {
    __shared__ unsigned As[128][20];       // [row][k] stride 20 (16 data + pad)
    __shared__ unsigned Bs[2][16][136];    // [mat][k][col] stride 136
    const float* __restrict__ X = xsel ? g_h : Xe;

    int tid = threadIdx.x;
    int wid = tid >> 5, lane = tid & 31;
    int mat = wid >> 3;             // 0 = P, 1 = Q
    int wm = (wid & 7) >> 1;        // 0..3  (row tile)
    int wn = wid & 1;               // 0..1  (col tile)
    int gid = lane >> 2, tig = lane & 3;
    int row0 = blockIdx.x * 128;

    float c[2][8][4];
    #pragma unroll
    for (int mi = 0; mi < 2; mi++)
        #pragma unroll
        for (int ni = 0; ni < 8; ni++)
            #pragma unroll
            for (int j = 0; j < 4; j++) c[mi][ni][j] = 0.f;

    int arow = tid >> 2;            // 0..127
    int acol = (tid & 3) * 4;       // 0,4,8,12
    int brow = tid >> 5;            // 0..15
    int bcol = (tid & 31) * 4;      // 0..124

    const float* xr = X + (size_t)(row0 + arow) * 128 + acol;
    bool aval = (row0 + arow) < n;

    for (int kk = 0; kk < 128; kk += 16) {
        __syncthreads();
        {
            float4 v = make_float4(0.f, 0.f, 0.f, 0.f);
            if (aval) v = *(const float4*)(xr + kk);
            As[arow][acol + 0] = tf32(v.x);
            As[arow][acol + 1] = tf32(v.y);
            As[arow][acol + 2] = tf32(v.z);
            As[arow][acol + 3] = tf32(v.w);
        }
        {
            float4 vl = *(const float4*)(Wl + (size_t)(kk + brow) * 128 + bcol);
            float4 vr = *(const float4*)(Wr + (size_t)(kk + brow) * 128 + bcol);
            Bs[0][brow][bcol + 0] = tf32(vl.x);
            Bs[0][brow][bcol + 1] = tf32(vl.y);
            Bs[0][brow][bcol + 2] = tf32(vl.z);
            Bs[0][brow][bcol + 3] = tf32(vl.w);
            Bs[1][brow][bcol + 0] = tf32(vr.x);
            Bs[1][brow][bcol + 1] = tf32(vr.y);
            Bs[1][brow][bcol + 2] = tf32(vr.z);
            Bs[1][brow][bcol + 3] = tf32(vr.w);
        }
        __syncthreads();

        #pragma unroll
        for (int ks = 0; ks < 2; ks++) {
            unsigned a[2][4], b[8][2];
            #pragma unroll
            for (int mi = 0; mi < 2; mi++) {
                int r = wm * 32 + mi * 16 + gid;
                a[mi][0] = As[r][ks * 8 + tig];
                a[mi][1] = As[r + 8][ks * 8 + tig];
                a[mi][2] = As[r][ks * 8 + tig + 4];
                a[mi][3] = As[r + 8][ks * 8 + tig + 4];
            }
            #pragma unroll
            for (int ni = 0; ni < 8; ni++) {
                int col = wn * 64 + ni * 8 + gid;
                b[ni][0] = Bs[mat][ks * 8 + tig][col];
                b[ni][1] = Bs[mat][ks * 8 + tig + 4][col];
            }
            #pragma unroll
            for (int mi = 0; mi < 2; mi++)
                #pragma unroll
                for (int ni = 0; ni < 8; ni++)
                    mma_tf32(c[mi][ni], a[mi], b[ni]);
        }
    }

    // epilogue
    if (mat == 0) {
        #pragma unroll
        for (int mi = 0; mi < 2; mi++) {
            int r = row0 + wm * 32 + mi * 16 + gid;
            #pragma unroll
            for (int ni = 0; ni < 8; ni++) {
                int cl = wn * 64 + ni * 8 + tig * 2;
                if (r < n)
                    g_pb[(size_t)r * 64 + (cl >> 1)] = pack_bf16x2(c[mi][ni][0], c[mi][ni][1]);
                if (r + 8 < n)
                    g_pb[(size_t)(r + 8) * 64 + (cl >> 1)] = pack_bf16x2(c[mi][ni][2], c[mi][ni][3]);
            }
        }
    } else {
        #pragma unroll
        for (int mi = 0; mi < 2; mi++) {
            int r = row0 + wm * 32 + mi * 16 + gid;
            #pragma unroll
            for (int ni = 0; ni < 8; ni++) {
                int cl = wn * 64 + ni * 8 + tig * 2;
                if (r < n)
                    *(float2*)(g_q + (size_t)r * 128 + cl) = make_float2(c[mi][ni][0], c[mi][ni][1]);
                if (r + 8 < n)
                    *(float2*)(g_q + (size_t)(r + 8) * 128 + cl) = make_float2(c[mi][ni][2], c[mi][ni][3]);
            }
        }
    }
}

// ---------------- aggregation: out = [relu]( mean_agg(Pb) + b + Q ) ---------
__global__ void k_agg(const float* __restrict__ bias, float* __restrict__ oext,
                      int osel, int do_relu) {
    int w = (blockIdx.x * blockDim.x + threadIdx.x) >> 5;
    if (w >= N_NODES) return;
    const unsigned* __restrict__ P = g_pb;
    const float* __restrict__ Q = g_q;
    float* __restrict__ out = osel ? oext : g_h;

    int lane = threadIdx.x & 31;
    int s0 = g_offs[w], s1 = g_offs[w + 1];

    float4 acc0 = make_float4(0.f, 0.f, 0.f, 0.f);
    float4 acc1 = make_float4(0.f, 0.f, 0.f, 0.f);
    int e = s0;
    for (; e + 8 <= s1; e += 8) {
        int idx[8];
        #pragma unroll
        for (int j = 0; j < 8; j++) idx[j] = g_esrc[e + j];
        uint2 u[8];
        #pragma unroll
        for (int j = 0; j < 8; j++)
            u[j] = ((const uint2*)(P + (size_t)idx[j] * 64))[lane];
        #pragma unroll
        for (int j = 0; j < 8; j += 2) {
            acc0.x += bf_lo(u[j].x) + bf_lo(u[j + 1].x);
            acc0.y += bf_hi(u[j].x) + bf_hi(u[j + 1].x);
            acc0.z += bf_lo(u[j].y) + bf_lo(u[j + 1].y);
            acc0.w += bf_hi(u[j].y) + bf_hi(u[j + 1].y);
        }
    }
    for (; e + 2 <= s1; e += 2) {
        int i0 = g_esrc[e], i1 = g_esrc[e + 1];
        uint2 u0 = ((const uint2*)(P + (size_t)i0 * 64))[lane];
        uint2 u1 = ((const uint2*)(P + (size_t)i1 * 64))[lane];
        acc1.x += bf_lo(u0.x) + bf_lo(u1.x);
        acc1.y += bf_hi(u0.x) + bf_hi(u1.x);
        acc1.z += bf_lo(u0.y) + bf_lo(u1.y);
        acc1.w += bf_hi(u0.y) + bf_hi(u1.y);
    }
    if (e < s1) {
        int i0 = g_esrc[e];
        uint2 u0 = ((const uint2*)(P + (size_t)i0 * 64))[lane];
        acc1.x += bf_lo(u0.x); acc1.y += bf_hi(u0.x);
        acc1.z += bf_lo(u0.y); acc1.w += bf_hi(u0.y);
    }
    acc0.x += acc1.x; acc0.y += acc1.y; acc0.z += acc1.z; acc0.w += acc1.w;

    int deg = s1 - s0;
    float scale = 1.0f / (float)(deg > 0 ? deg : 1);
    float4 qv = ((const float4*)(Q + (size_t)w * 128))[lane];
    float4 bv = ((const float4*)bias)[lane];
    float4 r;
    r.x = fmaf(acc0.x, scale, bv.x + qv.x);
    r.y = fmaf(acc0.y, scale, bv.y + qv.y);
    r.z = fmaf(acc0.z, scale, bv.z + qv.z);
    r.w = fmaf(acc0.w, scale, bv.w + qv.w);
    if (do_relu) {
        r.x = fmaxf(r.x, 0.f); r.y = fmaxf(r.y, 0.f);
        r.z = fmaxf(r.z, 0.f); r.w = fmaxf(r.w, 0.f);
    }
    ((float4*)(out + (size_t)w * 128))[lane] = r;
}

// ---------------- launch -----------------------------------------------------
// Fork/join: CSR build runs on a side stream concurrently with GEMM1 (no data
// dependency). kernel_launch is only called for correctness + capture, so the
// per-call stream/event creation never appears in the timed graph replays.
extern "C" void kernel_launch(void* const* d_in, const int* in_sizes, int n_in,
                              void* d_out, int out_size) {
    const float* x   = (const float*)d_in[0];
    const int*   ei  = (const int*)d_in[1];
    const float* W1l = (const float*)d_in[2];
    const float* b1  = (const float*)d_in[3];
    const float* W1r = (const float*)d_in[4];
    const float* W2l = (const float*)d_in[5];
    const float* b2  = (const float*)d_in[6];
    const float* W2r = (const float*)d_in[7];
    float* out = (float*)d_out;

    const int GEMM_GRID = (N_NODES + 127) / 128;      // 782
    const int EDGE_GRID = (N_EDGES + 255) / 256;
    const int AGG_GRID  = (N_NODES * 32 + 255) / 256;

    cudaStream_t s1;
    cudaEvent_t evFork, evJoin;
    cudaStreamCreateWithFlags(&s1, cudaStreamNonBlocking);
    cudaEventCreateWithFlags(&evFork, cudaEventDisableTiming);
    cudaEventCreateWithFlags(&evJoin, cudaEventDisableTiming);

    // fork
    cudaEventRecord(evFork, 0);
    cudaStreamWaitEvent(s1, evFork, 0);

    // ---- branch A (s1): CSR build (dst-grouped pull lists) ----
    k_detect<<<(N_NODES + 255) / 256, 256, 0, s1>>>(ei);
    k_hist<<<EDGE_GRID, 256, 0, s1>>>(ei);
    k_scan_blocks<<<SCAN_BLOCKS, 1024, 0, s1>>>(N_NODES);
    k_scan_sums<<<1, 32, 0, s1>>>(SCAN_BLOCKS);
    k_add_offs<<<SCAN_BLOCKS, 1024, 0, s1>>>(N_NODES, N_EDGES);
    k_fill<<<EDGE_GRID, 256, 0, s1>>>(ei);
    cudaEventRecord(evJoin, s1);

    // ---- branch B (stream 0): layer-1 dual GEMM (independent of CSR) ----
    k_gemm2<<<GEMM_GRID, 512>>>(x, 0, W1l, W1r, N_NODES);

    // join, then the dependent chain
    cudaStreamWaitEvent(0, evJoin, 0);
    k_agg<<<AGG_GRID, 256>>>(b1, out, 0, 1);
    k_gemm2<<<GEMM_GRID, 512>>>((const float*)0, 1, W2l, W2r, N_NODES);
    k_agg<<<AGG_GRID, 256>>>(b2, out, 1, 0);

    // streams/events intentionally not destroyed here: destroying objects that
    // participate in an active capture invalidates it; ~2 calls total, no leak risk.
}